// round 15
// baseline (speedup 1.0000x reference)
#include <cuda_runtime.h>
#include <math.h>
#include <stdint.h>

#define SEQ 4096
#define IND 1024
#define NH  16
#define HD  64
#define ODIM (NH * HD)   // 1024

typedef unsigned long long u64;

__device__ float g_Q[NH * SEQ * HD];
__device__ float g_K[NH * SEQ * HD];
__device__ float g_V[NH * SEQ * HD];

// ---- tf32 mma helpers -----------------------------------------------------
__device__ __forceinline__ uint32_t f2tf32(float f) {
    uint32_t r; asm("cvt.rna.tf32.f32 %0,%1;" : "=r"(r) : "f"(f)); return r;
}
__device__ __forceinline__ float ex2f(float x) {
    float r; asm("ex2.approx.f32 %0,%1;" : "=f"(r) : "f"(x)); return r;
}
// D(f32) += A(tf32,row) * B(tf32,col);  m16n8k8
// A frag: a0=(g,c) a1=(g+8,c) a2=(g,c+4) a3=(g+8,c+4)
// B frag: b0=(k=c,n=g) b1=(k=c+4,n=g)
// C frag: c0=(g,2c) c1=(g,2c+1) c2=(g+8,2c) c3=(g+8,2c+1)
__device__ __forceinline__ void mma_tf32(float* c, const uint32_t* a,
                                         uint32_t b0, uint32_t b1) {
    asm volatile("mma.sync.aligned.m16n8k8.row.col.f32.tf32.tf32.f32 "
                 "{%0,%1,%2,%3},{%4,%5,%6,%7},{%8,%9},{%0,%1,%2,%3};"
                 : "+f"(c[0]), "+f"(c[1]), "+f"(c[2]), "+f"(c[3])
                 : "r"(a[0]), "r"(a[1]), "r"(a[2]), "r"(a[3]),
                   "r"(b0), "r"(b1));
}

#define KSTR 72

// ---------------------------------------------------------------------------
// Kernel 1: QKV projection, M=32 rows/warp, BK=32, 128 thr, software-
// pipelined global loads (load kt+1 issued before compute kt).
// Smem: (128+32)*72*4 = 46080 B.
// ---------------------------------------------------------------------------
__global__ __launch_bounds__(128, 3) void qkv_mma(
    const float* __restrict__ H,
    const float* __restrict__ Wq, const float* __restrict__ Wk,
    const float* __restrict__ Wv,
    const float* __restrict__ Bq, const float* __restrict__ Bk,
    const float* __restrict__ Bv)
{
    extern __shared__ uint32_t sm[];
    uint32_t* Hs  = sm;                 // [128][72] paired-permuted k
    uint32_t* Wsm = sm + 128 * KSTR;    // [32][72]  natural [k][n]

    const float* W; const float* Bias; float* Out;
    if (blockIdx.z == 0)      { W = Wq; Bias = Bq; Out = g_Q; }
    else if (blockIdx.z == 1) { W = Wk; Bias = Bk; Out = g_K; }
    else                      { W = Wv; Bias = Bv; Out = g_V; }

    const int tid  = threadIdx.x;
    const int w    = tid >> 5;
    const int lane = tid & 31;
    const int g    = lane >> 2;
    const int c    = lane & 3;
    const int head = blockIdx.x;
    const int n0   = head * 64;
    const int s0   = blockIdx.y * 128;

    float oacc[8][8];
#pragma unroll
    for (int nf = 0; nf < 8; nf++)
#pragma unroll
        for (int i = 0; i < 8; i++) oacc[nf][i] = 0.0f;

    const int lrow = tid >> 2;
    const int lc   = tid & 3;
    const int wk   = tid >> 2;
    const int wn   = (tid & 3) * 4;

    float hp0[4][4], hp1[4][4];
    float4 wr[4];

    // prologue: load slab 0
#pragma unroll
    for (int p = 0; p < 4; p++) {
        const float* hrow = H + (size_t)(s0 + 32 * p + lrow) * IND;
#pragma unroll
        for (int m = 0; m < 4; m++) {
            hp0[p][m] = hrow[8 * m + lc];
            hp1[p][m] = hrow[8 * m + lc + 4];
        }
    }
    {
        const float* wrow = W + (size_t)wk * ODIM + n0 + wn;
#pragma unroll
        for (int j = 0; j < 4; j++) wr[j] = *(const float4*)(wrow + 16 * j);
    }

    for (int k0 = 0; k0 < IND; k0 += 32) {
        __syncthreads();   // prior iteration's fragment reads done
        // ---- smem stores from staged regs ----
#pragma unroll
        for (int p = 0; p < 4; p++) {
            uint32_t* hbase = &Hs[(32 * p + lrow) * KSTR + 2 * lc];
#pragma unroll
            for (int m = 0; m < 4; m++) {
                uint2 t; t.x = f2tf32(hp0[p][m]); t.y = f2tf32(hp1[p][m]);
                *(uint2*)(hbase + 8 * m) = t;
            }
        }
#pragma unroll
        for (int j = 0; j < 4; j++) {
            uint4 t;
            t.x = f2tf32(wr[j].x); t.y = f2tf32(wr[j].y);
            t.z = f2tf32(wr[j].z); t.w = f2tf32(wr[j].w);
            *(uint4*)&Wsm[wk * KSTR + wn + 16 * j] = t;
        }
        __syncthreads();

        // ---- prefetch next slab (latency hidden under MMAs below) ----
        if (k0 + 32 < IND) {
            const int kn = k0 + 32;
#pragma unroll
            for (int p = 0; p < 4; p++) {
                const float* hrow = H + (size_t)(s0 + 32 * p + lrow) * IND + kn;
#pragma unroll
                for (int m = 0; m < 4; m++) {
                    hp0[p][m] = hrow[8 * m + lc];
                    hp1[p][m] = hrow[8 * m + lc + 4];
                }
            }
            const float* wrow = W + (size_t)(kn + wk) * ODIM + n0 + wn;
#pragma unroll
            for (int j = 0; j < 4; j++) wr[j] = *(const float4*)(wrow + 16 * j);
        }

        // ---- MMAs: 4 kf x (2 tiles x 8 nf) ----
#pragma unroll
        for (int kf = 0; kf < 4; kf++) {
            uint2 aA0 = *(const uint2*)&Hs[(32 * w + g) * KSTR + 8 * kf + 2 * c];
            uint2 aB0 = *(const uint2*)&Hs[(32 * w + 8 + g) * KSTR + 8 * kf + 2 * c];
            uint2 aA1 = *(const uint2*)&Hs[(32 * w + 16 + g) * KSTR + 8 * kf + 2 * c];
            uint2 aB1 = *(const uint2*)&Hs[(32 * w + 24 + g) * KSTR + 8 * kf + 2 * c];
            uint32_t af0[4] = { aA0.x, aB0.x, aA0.y, aB0.y };
            uint32_t af1[4] = { aA1.x, aB1.x, aA1.y, aB1.y };
            const uint32_t* b0r = &Wsm[(8 * kf + c) * KSTR + g];
            const uint32_t* b1r = &Wsm[(8 * kf + c + 4) * KSTR + g];
#pragma unroll
            for (int nf = 0; nf < 8; nf++) {
                uint32_t b0 = b0r[8 * nf];
                uint32_t b1 = b1r[8 * nf];
                mma_tf32(&oacc[nf][0], af0, b0, b1);
                mma_tf32(&oacc[nf][4], af1, b0, b1);
            }
        }
    }

    // ---- bias + store both tiles ----
#pragma unroll
    for (int t = 0; t < 2; t++) {
        float* o0 = Out + ((size_t)head * SEQ + s0 + 32 * w + 16 * t + g) * HD + 2 * c;
        float* o1 = o0 + 8 * HD;
#pragma unroll
        for (int nf = 0; nf < 8; nf++) {
            float2 bb = *(const float2*)(Bias + n0 + 8 * nf + 2 * c);
            *(float2*)(o0 + 8 * nf) = make_float2(oacc[nf][4 * t + 0] + bb.x,
                                                  oacc[nf][4 * t + 1] + bb.y);
            *(float2*)(o1 + 8 * nf) = make_float2(oacc[nf][4 * t + 2] + bb.x,
                                                  oacc[nf][4 * t + 3] + bb.y);
        }
    }
}

// ---------------------------------------------------------------------------
// Kernel 2: attention, M=32/warp, key-chunk streaming, software-pipelined
// global loads (load kt+1 issued before compute kt).
// ---------------------------------------------------------------------------
__global__ __launch_bounds__(128, 2) void attn_mma(float* __restrict__ Out)
{
    extern __shared__ uint32_t sm[];
    uint32_t* Ksm = sm;               // [key][d-permuted] stride 72
    uint32_t* Vsm = sm + 64 * KSTR;   // [key][d]          stride 72

    const int tid  = threadIdx.x;
    const int w    = tid >> 5;        // 0..3
    const int lane = tid & 31;
    const int g    = lane >> 2;
    const int c    = lane & 3;
    const int qt   = blockIdx.x;
    const int head = blockIdx.y;

    const float* Qg = g_Q + ((size_t)head * SEQ + qt * 128 + 32 * w) * HD;
    const float* Kg = g_K + (size_t)head * SEQ * HD;
    const float* Vg = g_V + (size_t)head * SEQ * HD;

    const float QS = 0.125f * 1.44269504f;
    uint32_t qf[8][8];   // [kf][4t+i]
#pragma unroll
    for (int kf = 0; kf < 8; kf++)
#pragma unroll
        for (int t = 0; t < 2; t++) {
            qf[kf][4 * t + 0] = f2tf32(Qg[(size_t)(16 * t + g) * HD + 8 * kf + c] * QS);
            qf[kf][4 * t + 1] = f2tf32(Qg[(size_t)(16 * t + 8 + g) * HD + 8 * kf + c] * QS);
            qf[kf][4 * t + 2] = f2tf32(Qg[(size_t)(16 * t + g) * HD + 8 * kf + c + 4] * QS);
            qf[kf][4 * t + 3] = f2tf32(Qg[(size_t)(16 * t + 8 + g) * HD + 8 * kf + c + 4] * QS);
        }

    float oacc[8][8];    // [nf][4t+i]
#pragma unroll
    for (int nf = 0; nf < 8; nf++)
#pragma unroll
        for (int i = 0; i < 8; i++) oacc[nf][i] = 0.0f;
    float lsum[2][2] = {{0.0f, 0.0f}, {0.0f, 0.0f}};

    const int lkey0 = tid >> 2;       // 0..31 (+32 on pass 1)
    const int lc    = tid & 3;

    const int src0 = (lane & ~3) | (c >> 1);
    const int src1 = src0 + 2;
    const bool odd = (c & 1);

    float kp0[2][8], kp1[2][8];
    float4 vr[2][4];

    // prologue: load tile 0
#pragma unroll
    for (int p = 0; p < 2; p++) {
        const float* krow = Kg + ((size_t)(lkey0 + 32 * p)) * HD;
        const float* vrow = Vg + ((size_t)(lkey0 + 32 * p)) * HD + lc * 4;
#pragma unroll
        for (int m = 0; m < 8; m++) {
            kp0[p][m] = krow[8 * m + lc];
            kp1[p][m] = krow[8 * m + lc + 4];
        }
#pragma unroll
        for (int j = 0; j < 4; j++) vr[p][j] = *(const float4*)(vrow + 16 * j);
    }

    for (int kt = 0; kt < SEQ / 64; kt++) {
        __syncthreads();   // prior iteration's fragment reads done
        // ---- smem stores from staged regs ----
#pragma unroll
        for (int p = 0; p < 2; p++) {
            const int key = lkey0 + 32 * p;
#pragma unroll
            for (int m = 0; m < 8; m++) {
                uint2 t; t.x = f2tf32(kp0[p][m]); t.y = f2tf32(kp1[p][m]);
                *(uint2*)&Ksm[key * KSTR + 8 * m + 2 * lc] = t;
            }
#pragma unroll
            for (int j = 0; j < 4; j++) {
                uint4 t;
                t.x = f2tf32(vr[p][j].x); t.y = f2tf32(vr[p][j].y);
                t.z = f2tf32(vr[p][j].z); t.w = f2tf32(vr[p][j].w);
                *(uint4*)&Vsm[key * KSTR + lc * 4 + 16 * j] = t;
            }
        }
        __syncthreads();

        // ---- prefetch next tile (latency hidden under compute below) ----
        if (kt + 1 < SEQ / 64) {
#pragma unroll
            for (int p = 0; p < 2; p++) {
                const float* krow = Kg + ((size_t)(kt + 1) * 64 + lkey0 + 32 * p) * HD;
                const float* vrow = Vg + ((size_t)(kt + 1) * 64 + lkey0 + 32 * p) * HD + lc * 4;
#pragma unroll
                for (int m = 0; m < 8; m++) {
                    kp0[p][m] = krow[8 * m + lc];
                    kp1[p][m] = krow[8 * m + lc + 4];
                }
#pragma unroll
                for (int j = 0; j < 4; j++) vr[p][j] = *(const float4*)(vrow + 16 * j);
            }
        }

        // ---- stream 4 chunks of 16 keys ----
#pragma unroll
        for (int kc = 0; kc < 4; kc++) {
            float sacc[4][4];
#pragma unroll
            for (int q = 0; q < 4; q++)
#pragma unroll
                for (int i = 0; i < 4; i++) sacc[q][i] = 0.0f;

#pragma unroll
            for (int kf = 0; kf < 8; kf++) {
                uint2 b0 = *(const uint2*)&Ksm[(16 * kc + g) * KSTR + 8 * kf + 2 * c];
                uint2 b1 = *(const uint2*)&Ksm[(16 * kc + 8 + g) * KSTR + 8 * kf + 2 * c];
                mma_tf32(sacc[0], &qf[kf][0], b0.x, b0.y);
                mma_tf32(sacc[1], &qf[kf][0], b1.x, b1.y);
                mma_tf32(sacc[2], &qf[kf][4], b0.x, b0.y);
                mma_tf32(sacc[3], &qf[kf][4], b1.x, b1.y);
            }

            // softmax (base-2, no max) + C->A fragment shuffle
            uint32_t pf[4][4];
#pragma unroll
            for (int q = 0; q < 4; q++) {
                const int t = q >> 1;
                float e0 = ex2f(sacc[q][0]);
                float e1 = ex2f(sacc[q][1]);
                float e2 = ex2f(sacc[q][2]);
                float e3 = ex2f(sacc[q][3]);
                lsum[t][0] += e0 + e1;
                lsum[t][1] += e2 + e3;
                float x0 = __shfl_sync(0xffffffffu, e0, src0);
                float x1 = __shfl_sync(0xffffffffu, e1, src0);
                float y0 = __shfl_sync(0xffffffffu, e0, src1);
                float y1 = __shfl_sync(0xffffffffu, e1, src1);
                float x2 = __shfl_sync(0xffffffffu, e2, src0);
                float x3 = __shfl_sync(0xffffffffu, e3, src0);
                float y2 = __shfl_sync(0xffffffffu, e2, src1);
                float y3 = __shfl_sync(0xffffffffu, e3, src1);
                pf[q][0] = f2tf32(odd ? x1 : x0);
                pf[q][1] = f2tf32(odd ? x3 : x2);
                pf[q][2] = f2tf32(odd ? y1 : y0);
                pf[q][3] = f2tf32(odd ? y3 : y2);
            }

            // O += P V  (B-frag shared across both tiles)
#pragma unroll
            for (int nf = 0; nf < 8; nf++) {
#pragma unroll
                for (int f = 0; f < 2; f++) {
                    uint32_t b0 = Vsm[(16 * kc + 8 * f + c) * KSTR + 8 * nf + g];
                    uint32_t b1 = Vsm[(16 * kc + 8 * f + c + 4) * KSTR + 8 * nf + g];
                    mma_tf32(&oacc[nf][0], pf[f],     b0, b1);
                    mma_tf32(&oacc[nf][4], pf[2 + f], b0, b1);
                }
            }
        }
    }

    // ---- finish row sums ----
#pragma unroll
    for (int t = 0; t < 2; t++)
#pragma unroll
        for (int hh = 0; hh < 2; hh++) {
            float l = lsum[t][hh];
            l += __shfl_xor_sync(0xffffffffu, l, 1);
            l += __shfl_xor_sync(0xffffffffu, l, 2);
            lsum[t][hh] = 1.0f / l;
        }

    // ---- store O ----
#pragma unroll
    for (int t = 0; t < 2; t++) {
        float* o0 = Out + (size_t)(qt * 128 + 32 * w + 16 * t + g) * ODIM
                    + head * HD + 2 * c;
        float* o1 = o0 + 8 * ODIM;
        const float inv0 = lsum[t][0];
        const float inv8 = lsum[t][1];
#pragma unroll
        for (int nf = 0; nf < 8; nf++) {
            *(float2*)(o0 + 8 * nf) = make_float2(oacc[nf][4 * t + 0] * inv0,
                                                  oacc[nf][4 * t + 1] * inv0);
            *(float2*)(o1 + 8 * nf) = make_float2(oacc[nf][4 * t + 2] * inv8,
                                                  oacc[nf][4 * t + 3] * inv8);
        }
    }
}

// ---------------------------------------------------------------------------
extern "C" void kernel_launch(void* const* d_in, const int* in_sizes, int n_in,
                              void* d_out, int out_size)
{
    const float* h  = (const float*)d_in[0];
    const float* Wq = (const float*)d_in[1];
    const float* Wk = (const float*)d_in[2];
    const float* Wv = (const float*)d_in[3];
    const float* bq = (const float*)d_in[4];
    const float* bk = (const float*)d_in[5];
    const float* bv = (const float*)d_in[6];
    float* out = (float*)d_out;

    const int qkv_smem  = (128 + 32) * KSTR * 4;   // 46080 B
    const int attn_smem = 2 * 64 * KSTR * 4;       // 36864 B
    cudaFuncSetAttribute(qkv_mma,
                         cudaFuncAttributeMaxDynamicSharedMemorySize, qkv_smem);
    cudaFuncSetAttribute(attn_mma,
                         cudaFuncAttributeMaxDynamicSharedMemorySize, attn_smem);

    dim3 gemm_grid(NH, SEQ / 128, 3);
    qkv_mma<<<gemm_grid, 128, qkv_smem>>>(h, Wq, Wk, Wv, bq, bk, bv);

    dim3 attn_grid(SEQ / 128, NH);
    attn_mma<<<attn_grid, 128, attn_smem>>>(out);
}

// round 16
// speedup vs baseline: 1.1074x; 1.1074x over previous
#include <cuda_runtime.h>
#include <math.h>
#include <stdint.h>

#define SEQ 4096
#define IND 1024
#define NH  16
#define HD  64
#define ODIM (NH * HD)   // 1024

typedef unsigned long long u64;

__device__ float g_Q[NH * SEQ * HD];
__device__ float g_K[NH * SEQ * HD];
__device__ float g_V[NH * SEQ * HD];

// ---- tf32 mma helpers -----------------------------------------------------
__device__ __forceinline__ uint32_t f2tf32(float f) {
    uint32_t r; asm("cvt.rna.tf32.f32 %0,%1;" : "=r"(r) : "f"(f)); return r;
}
__device__ __forceinline__ float ex2f(float x) {
    float r; asm("ex2.approx.f32 %0,%1;" : "=f"(r) : "f"(x)); return r;
}
// D(f32) += A(tf32,row) * B(tf32,col);  m16n8k8
// A frag: a0=(g,c) a1=(g+8,c) a2=(g,c+4) a3=(g+8,c+4)
// B frag: b0=(k=c,n=g) b1=(k=c+4,n=g)
// C frag: c0=(g,2c) c1=(g,2c+1) c2=(g+8,2c) c3=(g+8,2c+1)
__device__ __forceinline__ void mma_tf32(float* c, const uint32_t* a,
                                         uint32_t b0, uint32_t b1) {
    asm volatile("mma.sync.aligned.m16n8k8.row.col.f32.tf32.tf32.f32 "
                 "{%0,%1,%2,%3},{%4,%5,%6,%7},{%8,%9},{%0,%1,%2,%3};"
                 : "+f"(c[0]), "+f"(c[1]), "+f"(c[2]), "+f"(c[3])
                 : "r"(a[0]), "r"(a[1]), "r"(a[2]), "r"(a[3]),
                   "r"(b0), "r"(b1));
}

#define KSTR 72
#define ABUF (2 * 64 * KSTR)   // words per attn double-buffer stage (K+V)

// ---------------------------------------------------------------------------
// Kernel 1: QKV projection, M=32 rows/warp, BK=32, 128 thr (R13 WIN verbatim).
// Smem: (128+32)*72*4 = 46080 B.
// ---------------------------------------------------------------------------
__global__ __launch_bounds__(128, 3) void qkv_mma(
    const float* __restrict__ H,
    const float* __restrict__ Wq, const float* __restrict__ Wk,
    const float* __restrict__ Wv,
    const float* __restrict__ Bq, const float* __restrict__ Bk,
    const float* __restrict__ Bv)
{
    extern __shared__ uint32_t sm[];
    uint32_t* Hs  = sm;                 // [128][72] paired-permuted k
    uint32_t* Wsm = sm + 128 * KSTR;    // [32][72]  natural [k][n]

    const float* W; const float* Bias; float* Out;
    if (blockIdx.z == 0)      { W = Wq; Bias = Bq; Out = g_Q; }
    else if (blockIdx.z == 1) { W = Wk; Bias = Bk; Out = g_K; }
    else                      { W = Wv; Bias = Bv; Out = g_V; }

    const int tid  = threadIdx.x;
    const int w    = tid >> 5;
    const int lane = tid & 31;
    const int g    = lane >> 2;
    const int c    = lane & 3;
    const int head = blockIdx.x;
    const int n0   = head * 64;
    const int s0   = blockIdx.y * 128;

    float oacc[8][8];
#pragma unroll
    for (int nf = 0; nf < 8; nf++)
#pragma unroll
        for (int i = 0; i < 8; i++) oacc[nf][i] = 0.0f;

    const int lrow = tid >> 2;
    const int lc   = tid & 3;
    const int wk   = tid >> 2;
    const int wn   = (tid & 3) * 4;

    for (int k0 = 0; k0 < IND; k0 += 32) {
        float hp0[4][4], hp1[4][4];
#pragma unroll
        for (int p = 0; p < 4; p++) {
            const float* hrow = H + (size_t)(s0 + 32 * p + lrow) * IND + k0;
#pragma unroll
            for (int m = 0; m < 4; m++) {
                hp0[p][m] = hrow[8 * m + lc];
                hp1[p][m] = hrow[8 * m + lc + 4];
            }
        }
        float4 wr[4];
        const float* wrow = W + (size_t)(k0 + wk) * ODIM + n0 + wn;
#pragma unroll
        for (int j = 0; j < 4; j++) wr[j] = *(const float4*)(wrow + 16 * j);

        __syncthreads();

#pragma unroll
        for (int p = 0; p < 4; p++) {
            uint32_t* hbase = &Hs[(32 * p + lrow) * KSTR + 2 * lc];
#pragma unroll
            for (int m = 0; m < 4; m++) {
                uint2 t; t.x = f2tf32(hp0[p][m]); t.y = f2tf32(hp1[p][m]);
                *(uint2*)(hbase + 8 * m) = t;
            }
        }
#pragma unroll
        for (int j = 0; j < 4; j++) {
            uint4 t;
            t.x = f2tf32(wr[j].x); t.y = f2tf32(wr[j].y);
            t.z = f2tf32(wr[j].z); t.w = f2tf32(wr[j].w);
            *(uint4*)&Wsm[wk * KSTR + wn + 16 * j] = t;
        }
        __syncthreads();

#pragma unroll
        for (int kf = 0; kf < 4; kf++) {
            uint2 aA0 = *(const uint2*)&Hs[(32 * w + g) * KSTR + 8 * kf + 2 * c];
            uint2 aB0 = *(const uint2*)&Hs[(32 * w + 8 + g) * KSTR + 8 * kf + 2 * c];
            uint2 aA1 = *(const uint2*)&Hs[(32 * w + 16 + g) * KSTR + 8 * kf + 2 * c];
            uint2 aB1 = *(const uint2*)&Hs[(32 * w + 24 + g) * KSTR + 8 * kf + 2 * c];
            uint32_t af0[4] = { aA0.x, aB0.x, aA0.y, aB0.y };
            uint32_t af1[4] = { aA1.x, aB1.x, aA1.y, aB1.y };
            const uint32_t* b0r = &Wsm[(8 * kf + c) * KSTR + g];
            const uint32_t* b1r = &Wsm[(8 * kf + c + 4) * KSTR + g];
#pragma unroll
            for (int nf = 0; nf < 8; nf++) {
                uint32_t b0 = b0r[8 * nf];
                uint32_t b1 = b1r[8 * nf];
                mma_tf32(&oacc[nf][0], af0, b0, b1);
                mma_tf32(&oacc[nf][4], af1, b0, b1);
            }
        }
    }

#pragma unroll
    for (int t = 0; t < 2; t++) {
        float* o0 = Out + ((size_t)head * SEQ + s0 + 32 * w + 16 * t + g) * HD + 2 * c;
        float* o1 = o0 + 8 * HD;
#pragma unroll
        for (int nf = 0; nf < 8; nf++) {
            float2 bb = *(const float2*)(Bias + n0 + 8 * nf + 2 * c);
            *(float2*)(o0 + 8 * nf) = make_float2(oacc[nf][4 * t + 0] + bb.x,
                                                  oacc[nf][4 * t + 1] + bb.y);
            *(float2*)(o1 + 8 * nf) = make_float2(oacc[nf][4 * t + 2] + bb.x,
                                                  oacc[nf][4 * t + 3] + bb.y);
        }
    }
}

// ---------------------------------------------------------------------------
// Kernel 2: attention, M=32/warp, key-chunk streaming (R13 structure) with
// DOUBLE-BUFFERED smem and ONE barrier per iteration.
// Safety: buf[kt&1]'s previous readers are compute(kt-2), sequenced before
// sync(kt-1); every warp passed sync(kt-1) before any STS(kt).
// Smem: 2 * (64*72 + 64*72) * 4 = 73728 B -> 2 CTAs/SM.
// ---------------------------------------------------------------------------
__global__ __launch_bounds__(128, 2) void attn_mma(float* __restrict__ Out)
{
    extern __shared__ uint32_t sm[];

    const int tid  = threadIdx.x;
    const int w    = tid >> 5;        // 0..3
    const int lane = tid & 31;
    const int g    = lane >> 2;
    const int c    = lane & 3;
    const int qt   = blockIdx.x;
    const int head = blockIdx.y;

    const float* Qg = g_Q + ((size_t)head * SEQ + qt * 128 + 32 * w) * HD;
    const float* Kg = g_K + (size_t)head * SEQ * HD;
    const float* Vg = g_V + (size_t)head * SEQ * HD;

    const float QS = 0.125f * 1.44269504f;
    uint32_t qf[8][8];   // [kf][4t+i]
#pragma unroll
    for (int kf = 0; kf < 8; kf++)
#pragma unroll
        for (int t = 0; t < 2; t++) {
            qf[kf][4 * t + 0] = f2tf32(Qg[(size_t)(16 * t + g) * HD + 8 * kf + c] * QS);
            qf[kf][4 * t + 1] = f2tf32(Qg[(size_t)(16 * t + 8 + g) * HD + 8 * kf + c] * QS);
            qf[kf][4 * t + 2] = f2tf32(Qg[(size_t)(16 * t + g) * HD + 8 * kf + c + 4] * QS);
            qf[kf][4 * t + 3] = f2tf32(Qg[(size_t)(16 * t + 8 + g) * HD + 8 * kf + c + 4] * QS);
        }

    float oacc[8][8];    // [nf][4t+i]
#pragma unroll
    for (int nf = 0; nf < 8; nf++)
#pragma unroll
        for (int i = 0; i < 8; i++) oacc[nf][i] = 0.0f;
    float lsum[2][2] = {{0.0f, 0.0f}, {0.0f, 0.0f}};

    const int lkey0 = tid >> 2;       // 0..31 (+32 on pass 1)
    const int lc    = tid & 3;

    const int src0 = (lane & ~3) | (c >> 1);
    const int src1 = src0 + 2;
    const bool odd = (c & 1);

    for (int kt = 0; kt < SEQ / 64; kt++) {
        uint32_t* Ksm = sm + (kt & 1) * ABUF;        // [key][d-perm] stride 72
        uint32_t* Vsm = Ksm + 64 * KSTR;             // [key][d]      stride 72

        // ---- global loads (short staging liveness: consumed by STS below) ----
        float kp0[2][8], kp1[2][8];
        float4 vr[2][4];
#pragma unroll
        for (int p = 0; p < 2; p++) {
            const float* krow = Kg + ((size_t)kt * 64 + lkey0 + 32 * p) * HD;
            const float* vrow = Vg + ((size_t)kt * 64 + lkey0 + 32 * p) * HD + lc * 4;
#pragma unroll
            for (int m = 0; m < 8; m++) {
                kp0[p][m] = krow[8 * m + lc];
                kp1[p][m] = krow[8 * m + lc + 4];
            }
#pragma unroll
            for (int j = 0; j < 4; j++) vr[p][j] = *(const float4*)(vrow + 16 * j);
        }

        // ---- smem stores to this iteration's buffer (no barrier needed:
        //      previous readers of this buffer finished before sync(kt-1)) ----
#pragma unroll
        for (int p = 0; p < 2; p++) {
            const int key = lkey0 + 32 * p;
#pragma unroll
            for (int m = 0; m < 8; m++) {
                uint2 t; t.x = f2tf32(kp0[p][m]); t.y = f2tf32(kp1[p][m]);
                *(uint2*)&Ksm[key * KSTR + 8 * m + 2 * lc] = t;
            }
#pragma unroll
            for (int j = 0; j < 4; j++) {
                uint4 t;
                t.x = f2tf32(vr[p][j].x); t.y = f2tf32(vr[p][j].y);
                t.z = f2tf32(vr[p][j].z); t.w = f2tf32(vr[p][j].w);
                *(uint4*)&Vsm[key * KSTR + lc * 4 + 16 * j] = t;
            }
        }
        __syncthreads();   // single barrier: buf[kt&1] fully written

        // ---- stream 4 chunks of 16 keys ----
#pragma unroll
        for (int kc = 0; kc < 4; kc++) {
            float sacc[4][4];
#pragma unroll
            for (int q = 0; q < 4; q++)
#pragma unroll
                for (int i = 0; i < 4; i++) sacc[q][i] = 0.0f;

#pragma unroll
            for (int kf = 0; kf < 8; kf++) {
                uint2 b0 = *(const uint2*)&Ksm[(16 * kc + g) * KSTR + 8 * kf + 2 * c];
                uint2 b1 = *(const uint2*)&Ksm[(16 * kc + 8 + g) * KSTR + 8 * kf + 2 * c];
                mma_tf32(sacc[0], &qf[kf][0], b0.x, b0.y);
                mma_tf32(sacc[1], &qf[kf][0], b1.x, b1.y);
                mma_tf32(sacc[2], &qf[kf][4], b0.x, b0.y);
                mma_tf32(sacc[3], &qf[kf][4], b1.x, b1.y);
            }

            // softmax (base-2, no max) + C->A fragment shuffle
            uint32_t pf[4][4];
#pragma unroll
            for (int q = 0; q < 4; q++) {
                const int t = q >> 1;
                float e0 = ex2f(sacc[q][0]);
                float e1 = ex2f(sacc[q][1]);
                float e2 = ex2f(sacc[q][2]);
                float e3 = ex2f(sacc[q][3]);
                lsum[t][0] += e0 + e1;
                lsum[t][1] += e2 + e3;
                float x0 = __shfl_sync(0xffffffffu, e0, src0);
                float x1 = __shfl_sync(0xffffffffu, e1, src0);
                float y0 = __shfl_sync(0xffffffffu, e0, src1);
                float y1 = __shfl_sync(0xffffffffu, e1, src1);
                float x2 = __shfl_sync(0xffffffffu, e2, src0);
                float x3 = __shfl_sync(0xffffffffu, e3, src0);
                float y2 = __shfl_sync(0xffffffffu, e2, src1);
                float y3 = __shfl_sync(0xffffffffu, e3, src1);
                pf[q][0] = f2tf32(odd ? x1 : x0);
                pf[q][1] = f2tf32(odd ? x3 : x2);
                pf[q][2] = f2tf32(odd ? y1 : y0);
                pf[q][3] = f2tf32(odd ? y3 : y2);
            }

            // O += P V  (B-frag shared across both tiles)
#pragma unroll
            for (int nf = 0; nf < 8; nf++) {
#pragma unroll
                for (int f = 0; f < 2; f++) {
                    uint32_t b0 = Vsm[(16 * kc + 8 * f + c) * KSTR + 8 * nf + g];
                    uint32_t b1 = Vsm[(16 * kc + 8 * f + c + 4) * KSTR + 8 * nf + g];
                    mma_tf32(&oacc[nf][0], pf[f],     b0, b1);
                    mma_tf32(&oacc[nf][4], pf[2 + f], b0, b1);
                }
            }
        }
    }

    // ---- finish row sums ----
#pragma unroll
    for (int t = 0; t < 2; t++)
#pragma unroll
        for (int hh = 0; hh < 2; hh++) {
            float l = lsum[t][hh];
            l += __shfl_xor_sync(0xffffffffu, l, 1);
            l += __shfl_xor_sync(0xffffffffu, l, 2);
            lsum[t][hh] = 1.0f / l;
        }

    // ---- store O ----
#pragma unroll
    for (int t = 0; t < 2; t++) {
        float* o0 = Out + (size_t)(qt * 128 + 32 * w + 16 * t + g) * ODIM
                    + head * HD + 2 * c;
        float* o1 = o0 + 8 * ODIM;
        const float inv0 = lsum[t][0];
        const float inv8 = lsum[t][1];
#pragma unroll
        for (int nf = 0; nf < 8; nf++) {
            *(float2*)(o0 + 8 * nf) = make_float2(oacc[nf][4 * t + 0] * inv0,
                                                  oacc[nf][4 * t + 1] * inv0);
            *(float2*)(o1 + 8 * nf) = make_float2(oacc[nf][4 * t + 2] * inv8,
                                                  oacc[nf][4 * t + 3] * inv8);
        }
    }
}

// ---------------------------------------------------------------------------
extern "C" void kernel_launch(void* const* d_in, const int* in_sizes, int n_in,
                              void* d_out, int out_size)
{
    const float* h  = (const float*)d_in[0];
    const float* Wq = (const float*)d_in[1];
    const float* Wk = (const float*)d_in[2];
    const float* Wv = (const float*)d_in[3];
    const float* bq = (const float*)d_in[4];
    const float* bk = (const float*)d_in[5];
    const float* bv = (const float*)d_in[6];
    float* out = (float*)d_out;

    const int qkv_smem  = (128 + 32) * KSTR * 4;   // 46080 B
    const int attn_smem = 2 * ABUF * 4;            // 73728 B
    cudaFuncSetAttribute(qkv_mma,
                         cudaFuncAttributeMaxDynamicSharedMemorySize, qkv_smem);
    cudaFuncSetAttribute(attn_mma,
                         cudaFuncAttributeMaxDynamicSharedMemorySize, attn_smem);

    dim3 gemm_grid(NH, SEQ / 128, 3);
    qkv_mma<<<gemm_grid, 128, qkv_smem>>>(h, Wq, Wk, Wv, bq, bk, bv);

    dim3 attn_grid(SEQ / 128, NH);
    attn_mma<<<attn_grid, 128, attn_smem>>>(out);
}